// round 2
// baseline (speedup 1.0000x reference)
#include <cuda_runtime.h>

#define NP    64      // patch size
#define CH    4       // channels
#define PAD   192     // canvas
#define TPB   512     // threads per block (one block per batch sample)
#define PIX   (PAD*PAD)          // 36864 pixels per sample
#define PATCH_FLOATS (NP*NP*CH)  // 16384 floats = 64KB

// out[b,y,x] = sum_c bilinear(patch_c centered, y-64-dy_c, x-64-dx_c), zero fill.
// Key identity: for integer y, floor(y-64-dy) = y + floor(-64-dy), and the
// fractional weight frac(-64-dy) is constant per (b,c). So the inner loop is
// integer offsets + 4 constant weights per channel.
__global__ __launch_bounds__(TPB)
void reassemble_smem_kernel(const float* __restrict__ patches,
                            const float* __restrict__ pos,
                            float* __restrict__ out)
{
    extern __shared__ float sm[];   // [CH][NP][NP] channel-major, 64KB
    const int b   = blockIdx.x;
    const int tid = threadIdx.x;

    // ---- Phase 1: load patch (B,64,64,4) -> smem channel-major, coalesced ----
    const float4* pin = reinterpret_cast<const float4*>(patches + (size_t)b * PATCH_FLOATS);
    #pragma unroll
    for (int i = 0; i < (PATCH_FLOATS / 4) / TPB; i++) {       // 8 iterations
        const int idx = i * TPB + tid;                          // (y*64 + x)
        const float4 v = pin[idx];                              // 4 channels of one pixel
        sm[0 * NP * NP + idx] = v.x;
        sm[1 * NP * NP + idx] = v.y;
        sm[2 * NP * NP + idx] = v.z;
        sm[3 * NP * NP + idx] = v.w;
    }

    // ---- Per-channel constants (broadcast loads, cheap) ----
    int   oxc[CH], oyc[CH];
    float w00[CH], w01[CH], w10[CH], w11[CH];
    const float* pb_pos = pos + (size_t)b * 2 * CH;
    #pragma unroll
    for (int c = 0; c < CH; c++) {
        const float dx = __ldg(pb_pos + c);
        const float dy = __ldg(pb_pos + CH + c);
        const float fx = -64.0f - dx;
        const float fy = -64.0f - dy;
        const float flx = floorf(fx);
        const float fly = floorf(fy);
        oxc[c] = (int)flx;
        oyc[c] = (int)fly;
        const float wx = fx - flx;          // constant fractional weights
        const float wy = fy - fly;
        w00[c] = (1.0f - wx) * (1.0f - wy);
        w01[c] = wx * (1.0f - wy);
        w10[c] = (1.0f - wx) * wy;
        w11[c] = wx * wy;
    }

    __syncthreads();

    // ---- Phase 2: one pixel per thread-iteration; lanes = consecutive x ----
    float* ob = out + (size_t)b * PIX;
    #pragma unroll 4
    for (int p = tid; p < PIX; p += TPB) {                      // 72 iterations
        const int y = p / PAD;
        const int x = p - y * PAD;
        float acc = 0.0f;

        #pragma unroll
        for (int c = 0; c < CH; c++) {
            const int iy = y + oyc[c];                          // top tap row
            if (iy < -1 || iy > NP - 1) continue;
            const int ix = x + oxc[c];                          // left tap col
            if (ix < -1 || ix > NP - 1) continue;

            const bool r0 = (iy >= 0);
            const bool r1 = (iy <= NP - 2);
            const bool c0 = (ix >= 0);
            const bool c1 = (ix <= NP - 2);
            const float* plane = sm + c * NP * NP;
            const int base = iy * NP + ix;

            const float t00 = (r0 && c0) ? plane[base]          : 0.0f;
            const float t01 = (r0 && c1) ? plane[base + 1]      : 0.0f;
            const float t10 = (r1 && c0) ? plane[base + NP]     : 0.0f;
            const float t11 = (r1 && c1) ? plane[base + NP + 1] : 0.0f;

            acc += t00 * w00[c] + t01 * w01[c] + t10 * w10[c] + t11 * w11[c];
        }
        ob[p] = acc;
    }
}

extern "C" void kernel_launch(void* const* d_in, const int* in_sizes, int n_in,
                              void* d_out, int out_size) {
    const float* patches = (const float*)d_in[0];   // (B, 64, 64, 4) fp32
    const float* pos     = (const float*)d_in[1];   // (B, 1, 2, 4)  fp32
    float* out           = (float*)d_out;           // (B, 192, 192, 1) fp32

    const int B = out_size / PIX;                   // 512
    const int smem_bytes = PATCH_FLOATS * sizeof(float);   // 64KB > 48KB default
    static bool attr_set = false;
    if (!attr_set) {
        cudaFuncSetAttribute(reassemble_smem_kernel,
                             cudaFuncAttributeMaxDynamicSharedMemorySize, smem_bytes);
        attr_set = true;
    }
    reassemble_smem_kernel<<<B, TPB, smem_bytes>>>(patches, pos, out);
}

// round 3
// speedup vs baseline: 1.3621x; 1.3621x over previous
#include <cuda_runtime.h>

#define NP    64                 // patch size
#define CH    4                  // channels
#define PAD   192                // canvas
#define TPB   256
#define PLW   72                 // padded plane width  (4 left, 4 right)
#define PLH   66                 // padded plane height (1 top, 1 bottom)
#define PLANE (PLW*PLH)          // 4752 floats per channel plane
#define SMF   (CH*PLANE)         // 19008 floats = 76,032 B
#define HQ    ((PAD/2)*(PAD/4))  // quads per half-canvas = 96*48 = 4608

// out[b,y,x] = sum_c bilinear(patch_c centered, y-64-dy_c, x-64-dx_c), zero fill.
// For integer (x,y): floor(y-64-dy) = y + floor(-64-dy); frac weights constant
// per (b,c). Patch planes staged in smem with a zero border so edge taps need
// no predicates.
__global__ __launch_bounds__(TPB, 3)
void reassemble_pad_kernel(const float* __restrict__ patches,
                           const float* __restrict__ pos,
                           float* __restrict__ out)
{
    extern __shared__ float sm[];        // CH planes of [PLH][PLW], zero border
    const int b    = blockIdx.x;
    const int half = blockIdx.y;         // 0 = rows [0,96), 1 = rows [96,192)
    const int tid  = threadIdx.x;

    // ---- zero all planes (covers the borders) ----
    float4* smv = reinterpret_cast<float4*>(sm);
    for (int i = tid; i < SMF / 4; i += TPB)
        smv[i] = make_float4(0.f, 0.f, 0.f, 0.f);
    __syncthreads();

    // ---- fill interior: (64,64,4) pixel-major -> 4 channel planes ----
    const float4* pin = reinterpret_cast<const float4*>(patches + (size_t)b * NP * NP * CH);
    #pragma unroll
    for (int i = 0; i < (NP * NP) / TPB; i++) {      // 16 iterations
        const int idx = i * TPB + tid;               // py*64 + px
        const float4 v = pin[idx];
        const int py = idx >> 6;
        const int px = idx & 63;
        const int o  = (py + 1) * PLW + (px + 4);
        sm[0 * PLANE + o] = v.x;
        sm[1 * PLANE + o] = v.y;
        sm[2 * PLANE + o] = v.z;
        sm[3 * PLANE + o] = v.w;
    }

    // ---- per-channel integer offsets + constant bilinear weights ----
    int   oxc[CH], oyc[CH];
    float w00[CH], w01[CH], w10[CH], w11[CH];
    const float* pb_pos = pos + (size_t)b * 2 * CH;
    #pragma unroll
    for (int c = 0; c < CH; c++) {
        const float dx = __ldg(pb_pos + c);
        const float dy = __ldg(pb_pos + CH + c);
        const float fx = -64.0f - dx;
        const float fy = -64.0f - dy;
        const float flx = floorf(fx), fly = floorf(fy);
        oxc[c] = (int)flx;
        oyc[c] = (int)fly;
        const float wx = fx - flx, wy = fy - fly;
        w00[c] = (1.0f - wx) * (1.0f - wy);
        w01[c] = wx * (1.0f - wy);
        w10[c] = (1.0f - wx) * wy;
        w11[c] = wx * wy;
    }
    __syncthreads();

    // ---- phase 2: 4 consecutive x-pixels per thread, float4 store ----
    const int ybase = half * (PAD / 2);
    float* ob = out + (size_t)b * PAD * PAD;

    #pragma unroll
    for (int q = 0; q < HQ / TPB; q++) {             // 18 iterations
        const int p4 = q * TPB + tid;                // quad index in half
        const int y  = ybase + p4 / (PAD / 4);       // /48
        const int x0 = (p4 % (PAD / 4)) * 4;

        float a0 = 0.f, a1 = 0.f, a2 = 0.f, a3 = 0.f;

        #pragma unroll
        for (int c = 0; c < CH; c++) {
            const int iy = y + oyc[c];               // top tap row (patch coords)
            if ((unsigned)(iy + 1) > 64u) continue;  // iy outside [-1, 63]
            const int ix = x0 + oxc[c];              // left tap col of pixel 0
            if (ix < -4 || ix > 63) continue;        // all 5 tap cols outside

            const float* r0 = sm + c * PLANE + (iy + 1) * PLW + (ix + 4);
            const float* r1 = r0 + PLW;
            const float vt0 = r0[0], vt1 = r0[1], vt2 = r0[2], vt3 = r0[3], vt4 = r0[4];
            const float vb0 = r1[0], vb1 = r1[1], vb2 = r1[2], vb3 = r1[3], vb4 = r1[4];

            const float W00 = w00[c], W01 = w01[c], W10 = w10[c], W11 = w11[c];
            a0 += vt0 * W00 + vt1 * W01 + vb0 * W10 + vb1 * W11;
            a1 += vt1 * W00 + vt2 * W01 + vb1 * W10 + vb2 * W11;
            a2 += vt2 * W00 + vt3 * W01 + vb2 * W10 + vb3 * W11;
            a3 += vt3 * W00 + vt4 * W01 + vb3 * W10 + vb4 * W11;
        }

        float4 o4; o4.x = a0; o4.y = a1; o4.z = a2; o4.w = a3;
        *reinterpret_cast<float4*>(ob + (size_t)y * PAD + x0) = o4;
    }
}

extern "C" void kernel_launch(void* const* d_in, const int* in_sizes, int n_in,
                              void* d_out, int out_size) {
    const float* patches = (const float*)d_in[0];   // (B, 64, 64, 4) fp32
    const float* pos     = (const float*)d_in[1];   // (B, 1, 2, 4)  fp32
    float* out           = (float*)d_out;           // (B, 192, 192, 1) fp32

    const int B = out_size / (PAD * PAD);           // 512
    const int smem_bytes = SMF * sizeof(float);     // 76,032 B
    static bool attr_set = false;
    if (!attr_set) {
        cudaFuncSetAttribute(reassemble_pad_kernel,
                             cudaFuncAttributeMaxDynamicSharedMemorySize, smem_bytes);
        attr_set = true;
    }
    dim3 grid(B, 2);
    reassemble_pad_kernel<<<grid, TPB, smem_bytes>>>(patches, pos, out);
}